// round 4
// baseline (speedup 1.0000x reference)
#include <cuda_runtime.h>
#include <math.h>

#define BB 8192

// ---------------- static scratch (no allocations allowed) ----------------
__device__ float g_W1f[1728];    __device__ float g_b1f[64];
__device__ float g_W2f[73728];   __device__ float g_b2f[128];
__device__ float g_W3f[294912];  __device__ float g_b3f[256];
__device__ float g_W4f[589824];  __device__ float g_b4f[256];
__device__ float g_p1[(size_t)BB * 6400];        // [B][64][10][10]
__device__ float g_p2[(size_t)BB * 3200];        // [B][128][25]
__device__ float g_c3[(size_t)BB * 6400];        // [B][25][256]  (p-major!)
__device__ float g_feats[(size_t)25 * BB * 256]; // [node][B][256]
__device__ float g_H[(size_t)25 * BB * 600];     // [node][B][600]
__device__ float g_preds[(size_t)25 * BB * 10];  // [node][B][10]
__device__ float g_nb[(size_t)25 * BB * 80];     // [node][B][80]

// ---------------- BN fold: Wf[(ci*9+k)*CO+o] = W[o][ci][k]*s;  bf[o] ----------------
__global__ void fold_kernel(const float* __restrict__ W, const float* __restrict__ bias,
                            const float* __restrict__ g, const float* __restrict__ be,
                            const float* __restrict__ m, const float* __restrict__ v,
                            float* __restrict__ Wf, float* __restrict__ bf, int CO, int CI) {
    int idx = blockIdx.x * 256 + threadIdx.x;
    int tot = CO * CI * 9;
    if (idx < tot) {
        int o = idx / (CI * 9); int rem = idx % (CI * 9); int ci = rem / 9; int k = rem % 9;
        float s = g[o] * rsqrtf(v[o] + 1e-5f);
        Wf[(ci * 9 + k) * CO + o] = W[idx] * s;
    }
    if (idx < CO) {
        float s = g[idx] * rsqrtf(v[idx] + 1e-5f);
        bf[idx] = (bias[idx] - m[idx]) * s + be[idx];
    }
}

// ---------------- conv1 (3->64, 20x20) + BN + ReLU + maxpool 3s2p1 -> [B][64][10][10] ----------------
__global__ __launch_bounds__(256) void conv1_kernel(const float* __restrict__ x,
                                                    const float* __restrict__ Wf,
                                                    const float* __restrict__ bf,
                                                    float* __restrict__ out) {
    extern __shared__ float sm[];
    float* inp = sm;                 // 3*22*22 = 1452 (zero-padded)
    float* ws  = sm + 1452;          // 27*64 = 1728
    float* co  = sm + 1452 + 1728;   // 64*400
    int b = blockIdx.x, t = threadIdx.x;
    for (int i = t; i < 1452; i += 256) inp[i] = 0.f;
    for (int i = t; i < 1728; i += 256) ws[i] = Wf[i];
    __syncthreads();
    const float* xb = x + (size_t)b * 1200;
    for (int i = t; i < 1200; i += 256) {
        int ci = i / 400, p = i % 400, y = p / 20, xx = p % 20;
        inp[ci * 484 + (y + 1) * 22 + (xx + 1)] = xb[i];
    }
    __syncthreads();
    for (int o = t; o < 25600; o += 256) {
        int oc = o / 400, p = o % 400, y = p / 20, xx = p % 20;
        float acc = bf[oc];
        #pragma unroll
        for (int ci = 0; ci < 3; ci++)
            #pragma unroll
            for (int ky = 0; ky < 3; ky++)
                #pragma unroll
                for (int kx = 0; kx < 3; kx++)
                    acc += ws[(ci * 9 + ky * 3 + kx) * 64 + oc] *
                           inp[ci * 484 + (y + ky) * 22 + (xx + kx)];
        co[o] = fmaxf(acc, 0.f);
    }
    __syncthreads();
    float* ob = out + (size_t)b * 6400;
    for (int o = t; o < 6400; o += 256) {
        int oc = o / 100, p = o % 100, pr = p / 10, pc = p % 10;
        float mv = 0.f;  // ReLU outputs >= 0
        #pragma unroll
        for (int dy = -1; dy <= 1; dy++) { int iy = 2 * pr + dy; if (iy < 0 || iy > 19) continue;
            #pragma unroll
            for (int dx = -1; dx <= 1; dx++) { int ix = 2 * pc + dx; if (ix < 0 || ix > 19) continue;
                mv = fmaxf(mv, co[oc * 400 + iy * 20 + ix]); } }
        ob[o] = mv;
    }
}

// ---------------- conv2 (64->128, 10x10) + BN + ReLU + pool -> [B][128][25] ----------------
__global__ __launch_bounds__(320) void conv2_kernel(const float* __restrict__ in,
                                                    const float* __restrict__ Wf,
                                                    const float* __restrict__ bf,
                                                    float* __restrict__ out) {
    extern __shared__ float sm[];
    float* inp = sm;                  // 64*12*12 = 9216 padded
    float* ws  = sm + 9216;           // 16*9*128 = 18432
    float* co  = sm + 9216 + 18432;   // 128*100
    int b = blockIdx.x, t = threadIdx.x;
    for (int i = t; i < 9216; i += 320) inp[i] = 0.f;
    __syncthreads();
    const float* ib = in + (size_t)b * 6400;
    for (int i = t; i < 6400; i += 320) {
        int ci = i / 100, p = i % 100, y = p / 10, xx = p % 10;
        inp[ci * 144 + (y + 1) * 12 + (xx + 1)] = ib[i];
    }
    int oc0 = (t % 32) * 4, row = t / 32;  // row 0..9
    float acc[4][10];
    #pragma unroll
    for (int j = 0; j < 4; j++)
        #pragma unroll
        for (int c = 0; c < 10; c++) acc[j][c] = 0.f;
    for (int cb = 0; cb < 64; cb += 16) {
        __syncthreads();
        const float4* wsrc = (const float4*)(Wf + cb * 1152);
        for (int i = t; i < 4608; i += 320) ((float4*)ws)[i] = wsrc[i];
        __syncthreads();
        for (int ci = 0; ci < 16; ci++) {
            const float* irow = inp + (cb + ci) * 144;
            #pragma unroll
            for (int ky = 0; ky < 3; ky++) {
                float r[12];
                #pragma unroll
                for (int q = 0; q < 12; q++) r[q] = irow[(row + ky) * 12 + q];
                const float* wrow = ws + (ci * 9 + ky * 3) * 128 + oc0;
                #pragma unroll
                for (int kx = 0; kx < 3; kx++) {
                    float4 w4 = *(const float4*)(wrow + kx * 128);
                    #pragma unroll
                    for (int c = 0; c < 10; c++) {
                        float iv = r[c + kx];
                        acc[0][c] += w4.x * iv; acc[1][c] += w4.y * iv;
                        acc[2][c] += w4.z * iv; acc[3][c] += w4.w * iv;
                    }
                }
            }
        }
    }
    __syncthreads();
    #pragma unroll
    for (int j = 0; j < 4; j++) {
        float bb = bf[oc0 + j];
        #pragma unroll
        for (int c = 0; c < 10; c++)
            co[(oc0 + j) * 100 + row * 10 + c] = fmaxf(acc[j][c] + bb, 0.f);
    }
    __syncthreads();
    float* ob = out + (size_t)b * 3200;
    for (int o = t; o < 3200; o += 320) {
        int oc = o / 25, p = o % 25, pr = p / 5, pc = p % 5;
        float mv = 0.f;
        #pragma unroll
        for (int dy = -1; dy <= 1; dy++) { int iy = 2 * pr + dy; if (iy < 0 || iy > 9) continue;
            #pragma unroll
            for (int dx = -1; dx <= 1; dx++) { int ix = 2 * pc + dx; if (ix < 0 || ix > 9) continue;
                mv = fmaxf(mv, co[oc * 100 + iy * 10 + ix]); } }
        ob[o] = mv;
    }
}

// ---------------- conv3/conv4 (CI->256, 5x5) + BN + ReLU ----------------
// MODE 0 (conv3): in [B][CI][25], out [B][25][256]
// MODE 1 (conv4): in [B][25][CI], out feats [node][B][256]
template<int CI, int MODE>
__global__ __launch_bounds__(320) void conv5x5_kernel(const float* __restrict__ in,
                                                      const float* __restrict__ Wf,
                                                      const float* __restrict__ bf,
                                                      float* __restrict__ out) {
    extern __shared__ float sm[];
    float* inp = sm;                 // CI*49 padded
    float* ws  = sm + CI * 49;       // 8*9*256 = 18432
    int b = blockIdx.x, t = threadIdx.x;
    for (int i = t; i < CI * 49; i += 320) inp[i] = 0.f;
    __syncthreads();
    const float* ib = in + (size_t)b * CI * 25;
    for (int i = t; i < CI * 25; i += 320) {
        int ci, p;
        if (MODE == 0) { ci = i / 25; p = i % 25; }
        else           { p = i / CI;  ci = i % CI; }
        inp[ci * 49 + (p / 5 + 1) * 7 + (p % 5) + 1] = ib[i];
    }
    int oc0 = (t % 64) * 4, row = t / 64;  // row 0..4
    float acc[4][5];
    #pragma unroll
    for (int j = 0; j < 4; j++)
        #pragma unroll
        for (int c = 0; c < 5; c++) acc[j][c] = 0.f;
    for (int cb = 0; cb < CI; cb += 8) {
        __syncthreads();
        const float4* wsrc = (const float4*)(Wf + cb * 2304);
        for (int i = t; i < 4608; i += 320) ((float4*)ws)[i] = wsrc[i];
        __syncthreads();
        #pragma unroll
        for (int ci = 0; ci < 8; ci++) {
            const float* irow = inp + (cb + ci) * 49;
            #pragma unroll
            for (int ky = 0; ky < 3; ky++) {
                float r[7];
                #pragma unroll
                for (int q = 0; q < 7; q++) r[q] = irow[(row + ky) * 7 + q];
                const float* wrow = ws + (ci * 9 + ky * 3) * 256 + oc0;
                #pragma unroll
                for (int kx = 0; kx < 3; kx++) {
                    float4 w4 = *(const float4*)(wrow + kx * 256);
                    #pragma unroll
                    for (int c = 0; c < 5; c++) {
                        float iv = r[c + kx];
                        acc[0][c] += w4.x * iv; acc[1][c] += w4.y * iv;
                        acc[2][c] += w4.z * iv; acc[3][c] += w4.w * iv;
                    }
                }
            }
        }
    }
    float4 bb4 = *(const float4*)(bf + oc0);
    #pragma unroll
    for (int c = 0; c < 5; c++) {
        float4 v;
        v.x = fmaxf(acc[0][c] + bb4.x, 0.f);
        v.y = fmaxf(acc[1][c] + bb4.y, 0.f);
        v.z = fmaxf(acc[2][c] + bb4.z, 0.f);
        v.w = fmaxf(acc[3][c] + bb4.w, 0.f);
        int p = row * 5 + c;
        if (MODE == 0)
            *(float4*)(out + (size_t)b * 6400 + p * 256 + oc0) = v;
        else
            *(float4*)(out + ((size_t)p * BB + b) * 256 + oc0) = v;
    }
}

// ---------------- MLP GEMM: H[node][b][c] = tanh(A @ Wa_part + ba), tiles 128x64xK ----------------
template<int STAGE>
__global__ __launch_bounds__(256) void gemm_mlp_kernel(const float* __restrict__ feats,
                                                       const float* __restrict__ nb,
                                                       const float* __restrict__ Wa,
                                                       const float* __restrict__ ba,
                                                       float* __restrict__ H) {
    const int K = (STAGE == 1) ? 256 : 336;
    int node = blockIdx.z;
    int m0 = blockIdx.x * 128;
    int c0 = blockIdx.y * 64;
    const float* Bmat = Wa + (size_t)node * 201600 + ((STAGE == 1) ? 80 : 0) * 600;
    const float* A1 = feats + (size_t)node * BB * 256;
    const float* A0 = (STAGE == 2) ? (nb + (size_t)node * BB * 80) : nullptr;

    __shared__ float As[8][132];
    __shared__ float Bs[8][64];

    int t = threadIdx.x;
    int rm = (t / 16) * 8;
    int cn = (t % 16) * 4;
    float acc[8][4];
    #pragma unroll
    for (int i = 0; i < 8; i++)
        #pragma unroll
        for (int j = 0; j < 4; j++) acc[i][j] = 0.f;

    int lm = t >> 1, lkq = (t & 1) * 4;          // A loader
    int lbk = t >> 5, lbc = (t & 31) * 2;        // B loader

    for (int k0 = 0; k0 < K; k0 += 8) {
        {
            int gk = k0 + lkq;
            float4 v;
            if (STAGE == 2 && gk < 80)
                v = *(const float4*)(A0 + (size_t)(m0 + lm) * 80 + gk);
            else {
                int gg = (STAGE == 2) ? gk - 80 : gk;
                v = *(const float4*)(A1 + (size_t)(m0 + lm) * 256 + gg);
            }
            As[lkq][lm] = v.x; As[lkq + 1][lm] = v.y;
            As[lkq + 2][lm] = v.z; As[lkq + 3][lm] = v.w;
        }
        {
            int gc = c0 + lbc;
            float2 v = make_float2(0.f, 0.f);
            if (gc < 600) v = *(const float2*)(Bmat + (size_t)(k0 + lbk) * 600 + gc);
            Bs[lbk][lbc] = v.x; Bs[lbk][lbc + 1] = v.y;
        }
        __syncthreads();
        #pragma unroll
        for (int kk = 0; kk < 8; kk++) {
            float4 a0 = *(const float4*)&As[kk][rm];
            float4 a1 = *(const float4*)&As[kk][rm + 4];
            float4 bv = *(const float4*)&Bs[kk][cn];
            float a[8] = {a0.x, a0.y, a0.z, a0.w, a1.x, a1.y, a1.z, a1.w};
            float bj[4] = {bv.x, bv.y, bv.z, bv.w};
            #pragma unroll
            for (int i = 0; i < 8; i++)
                #pragma unroll
                for (int j = 0; j < 4; j++)
                    acc[i][j] += a[i] * bj[j];
        }
        __syncthreads();
    }
    const float* bap = ba + node * 600;
    float* Hp = H + (size_t)node * BB * 600;
    #pragma unroll
    for (int i = 0; i < 8; i++) {
        int bidx = m0 + rm + i;
        #pragma unroll
        for (int j = 0; j < 4; j++) {
            int c = c0 + cn + j;
            if (c < 600) Hp[(size_t)bidx * 600 + c] = tanhf(acc[i][j] + bap[c]);
        }
    }
}

// ---------------- logits + softmax: warp per row ----------------
__global__ __launch_bounds__(256) void logits_kernel(const float* __restrict__ H,
                                                     const float* __restrict__ Wb,
                                                     const float* __restrict__ bbias,
                                                     float* __restrict__ out) {
    int node = blockIdx.y;
    __shared__ float WbT[10][600];
    __shared__ float bbs[10];
    const float* w = Wb + (size_t)node * 6000;
    for (int i = threadIdx.x; i < 6000; i += 256) {
        int j = i / 10, c = i % 10;
        WbT[c][j] = w[i];
    }
    if (threadIdx.x < 10) bbs[threadIdx.x] = bbias[node * 10 + threadIdx.x];
    __syncthreads();
    int warp = threadIdx.x >> 5, lane = threadIdx.x & 31;
    int b = blockIdx.x * 8 + warp;
    const float* h = H + ((size_t)node * BB + b) * 600;
    float p[10];
    #pragma unroll
    for (int c = 0; c < 10; c++) p[c] = 0.f;
    for (int j = lane; j < 600; j += 32) {
        float hv = h[j];
        #pragma unroll
        for (int c = 0; c < 10; c++) p[c] += hv * WbT[c][j];
    }
    #pragma unroll
    for (int off = 16; off; off >>= 1)
        #pragma unroll
        for (int c = 0; c < 10; c++) p[c] += __shfl_xor_sync(0xffffffffu, p[c], off);
    float mx = -1e30f;
    #pragma unroll
    for (int c = 0; c < 10; c++) { p[c] += bbs[c]; mx = fmaxf(mx, p[c]); }
    float s = 0.f;
    #pragma unroll
    for (int c = 0; c < 10; c++) { p[c] = __expf(p[c] - mx); s += p[c]; }
    float inv = 1.f / s;
    if (lane < 10) out[((size_t)node * BB + b) * 10 + lane] = p[lane] * inv;
}

// ---------------- neighbor gather: nb[n][b][s*10+c] ----------------
__global__ void gather_kernel(const float* __restrict__ preds, float* __restrict__ nbuf) {
    long long idx = (long long)blockIdx.x * 256 + threadIdx.x;
    if (idx >= 25LL * BB * 80) return;
    int c = (int)(idx % 10);
    long long r = idx / 10;
    int s = (int)(r % 8); r /= 8;
    int b = (int)(r % BB);
    int i = (int)(r / BB);
    const int w = 5, size = 25;
    int nl[8]; int cnt = 0;
    if (i - w >= 0) nl[cnt++] = i - w;
    if (i % w != 0) nl[cnt++] = i - 1;
    if ((i + 1) % w != 0) nl[cnt++] = i + 1;
    if (i + w < size) nl[cnt++] = i + w;
    if (i - w - 1 >= 0 && i % w != 0) nl[cnt++] = i - w - 1;
    if (i - w + 1 >= 0 && (i + 1) % w != 0) nl[cnt++] = i - w + 1;
    if (i + w - 1 < size && i % w != 0) nl[cnt++] = i + w - 1;
    if (i + w + 1 < size && (i + 1) % w != 0) nl[cnt++] = i + w + 1;
    while (cnt < 8) nl[cnt++] = -1;
    int id = nl[s];
    nbuf[idx] = (id >= 0) ? preds[((size_t)id * BB + b) * 10 + c] : 0.f;
}

// ---------------- mean over 25 nodes ----------------
__global__ void mean_kernel(const float* __restrict__ second, float* __restrict__ outm) {
    int idx = blockIdx.x * 256 + threadIdx.x;
    if (idx >= BB * 10) return;
    int b = idx / 10, c = idx % 10;
    float s = 0.f;
    #pragma unroll
    for (int n = 0; n < 25; n++) s += second[((size_t)n * BB + b) * 10 + c];
    outm[idx] = s * 0.04f;
}

// ---------------- launch ----------------
extern "C" void kernel_launch(void* const* d_in, const int* in_sizes, int n_in,
                              void* d_out, int out_size) {
    const float* x  = (const float*)d_in[0];
    const float* W1 = (const float*)d_in[1];  const float* b1 = (const float*)d_in[2];
    const float* g1 = (const float*)d_in[3];  const float* be1 = (const float*)d_in[4];
    const float* m1 = (const float*)d_in[5];  const float* v1 = (const float*)d_in[6];
    const float* W2 = (const float*)d_in[7];  const float* b2 = (const float*)d_in[8];
    const float* g2 = (const float*)d_in[9];  const float* be2 = (const float*)d_in[10];
    const float* m2 = (const float*)d_in[11]; const float* v2 = (const float*)d_in[12];
    const float* W3 = (const float*)d_in[13]; const float* b3 = (const float*)d_in[14];
    const float* g3 = (const float*)d_in[15]; const float* be3 = (const float*)d_in[16];
    const float* m3 = (const float*)d_in[17]; const float* v3 = (const float*)d_in[18];
    const float* W4 = (const float*)d_in[19]; const float* b4 = (const float*)d_in[20];
    const float* g4 = (const float*)d_in[21]; const float* be4 = (const float*)d_in[22];
    const float* m4 = (const float*)d_in[23]; const float* v4 = (const float*)d_in[24];
    const float* Wa = (const float*)d_in[25]; const float* ba = (const float*)d_in[26];
    const float* Wb = (const float*)d_in[27]; const float* bbv = (const float*)d_in[28];
    float* out = (float*)d_out;

    float *p1, *p2, *c3, *feats, *H, *preds, *nb;
    float *w1f, *b1f, *w2f, *b2f, *w3f, *b3f, *w4f, *b4f;
    cudaGetSymbolAddress((void**)&p1, g_p1);    cudaGetSymbolAddress((void**)&p2, g_p2);
    cudaGetSymbolAddress((void**)&c3, g_c3);    cudaGetSymbolAddress((void**)&feats, g_feats);
    cudaGetSymbolAddress((void**)&H, g_H);      cudaGetSymbolAddress((void**)&preds, g_preds);
    cudaGetSymbolAddress((void**)&nb, g_nb);
    cudaGetSymbolAddress((void**)&w1f, g_W1f);  cudaGetSymbolAddress((void**)&b1f, g_b1f);
    cudaGetSymbolAddress((void**)&w2f, g_W2f);  cudaGetSymbolAddress((void**)&b2f, g_b2f);
    cudaGetSymbolAddress((void**)&w3f, g_W3f);  cudaGetSymbolAddress((void**)&b3f, g_b3f);
    cudaGetSymbolAddress((void**)&w4f, g_W4f);  cudaGetSymbolAddress((void**)&b4f, g_b4f);

    const int smem1 = 115120, smem2 = 161792, smem3 = 98816, smem4 = 123904;
    cudaFuncSetAttribute(conv1_kernel, cudaFuncAttributeMaxDynamicSharedMemorySize, smem1);
    cudaFuncSetAttribute(conv2_kernel, cudaFuncAttributeMaxDynamicSharedMemorySize, smem2);
    cudaFuncSetAttribute(conv5x5_kernel<128, 0>, cudaFuncAttributeMaxDynamicSharedMemorySize, smem3);
    cudaFuncSetAttribute(conv5x5_kernel<256, 1>, cudaFuncAttributeMaxDynamicSharedMemorySize, smem4);

    // fold BN into weights
    fold_kernel<<<(64 * 3 * 9 + 255) / 256, 256>>>(W1, b1, g1, be1, m1, v1, w1f, b1f, 64, 3);
    fold_kernel<<<(128 * 64 * 9 + 255) / 256, 256>>>(W2, b2, g2, be2, m2, v2, w2f, b2f, 128, 64);
    fold_kernel<<<(256 * 128 * 9 + 255) / 256, 256>>>(W3, b3, g3, be3, m3, v3, w3f, b3f, 256, 128);
    fold_kernel<<<(256 * 256 * 9 + 255) / 256, 256>>>(W4, b4, g4, be4, m4, v4, w4f, b4f, 256, 256);

    conv1_kernel<<<BB, 256, smem1>>>(x, w1f, b1f, p1);
    conv2_kernel<<<BB, 320, smem2>>>(p1, w2f, b2f, p2);
    conv5x5_kernel<128, 0><<<BB, 320, smem3>>>(p2, w3f, b3f, c3);
    conv5x5_kernel<256, 1><<<BB, 320, smem4>>>(c3, w4f, b4f, feats);

    dim3 ggrid(BB / 128, 10, 25);
    gemm_mlp_kernel<1><<<ggrid, 256>>>(feats, nullptr, Wa, ba, H);
    dim3 lgrid(BB / 8, 25);
    logits_kernel<<<lgrid, 256>>>(H, Wb, bbv, preds);

    gather_kernel<<<(int)((25LL * BB * 80 + 255) / 256), 256>>>(preds, nb);

    gemm_mlp_kernel<2><<<ggrid, 256>>>(feats, nb, Wa, ba, H);
    logits_kernel<<<lgrid, 256>>>(H, Wb, bbv, out + BB * 10);

    mean_kernel<<<(BB * 10 + 255) / 256, 256>>>(out + BB * 10, out);
}